// round 1
// baseline (speedup 1.0000x reference)
#include <cuda_runtime.h>
#include <cuda_fp16.h>
#include <math.h>

#define S_DIM 2048
#define B_DIM 32
#define D_DIM 1024
#define H_DIM 16
#define HD 64
#define NTOK (S_DIM*B_DIM)
#define MT 32
#define THREADS 512
#define LN_EPS 1e-5f

// smem layout in 32-bit words
#define YSTRIDE 1032
#define OFF_SG   0
#define OFF_SB   (OFF_SG + 1024)
#define OFF_BIAS (OFF_SB + 1024)
#define OFF_MU   (OFF_BIAS + 1024)
#define OFF_RS   (OFF_MU + 32)
#define OFF_Y    (OFF_RS + 32)
#define OFF_AHI  (OFF_Y + 32*YSTRIDE)
#define OFF_ALO  (OFF_AHI + 32*68)
#define OFF_WHI  (OFF_ALO + 32*68)
#define OFF_WLO  (OFF_WHI + 64*72)
#define SMEM_WORDS (OFF_WLO + 64*72)

__device__ __forceinline__ void mma16816(float* d, const unsigned* a, unsigned b0, unsigned b1) {
    asm volatile(
        "mma.sync.aligned.m16n8k16.row.col.f32.f16.f16.f32 "
        "{%0,%1,%2,%3}, {%4,%5,%6,%7}, {%8,%9}, {%0,%1,%2,%3};\n"
        : "+f"(d[0]), "+f"(d[1]), "+f"(d[2]), "+f"(d[3])
        : "r"(a[0]), "r"(a[1]), "r"(a[2]), "r"(a[3]), "r"(b0), "r"(b1));
}

__device__ __forceinline__ unsigned split_pack_hi(float v0, float v1, unsigned& lo_out) {
    __half h0 = __float2half_rn(v0), h1 = __float2half_rn(v1);
    __half l0 = __float2half_rn(v0 - __half2float(h0));
    __half l1 = __float2half_rn(v1 - __half2float(h1));
    lo_out = (unsigned)__half_as_ushort(l0) | ((unsigned)__half_as_ushort(l1) << 16);
    return (unsigned)__half_as_ushort(h0) | ((unsigned)__half_as_ushort(h1) << 16);
}

__device__ __forceinline__ float gelu_exact(float v) {
    return 0.5f * v * (1.0f + erff(v * 0.70710678118654752f));
}

__global__ void __launch_bounds__(THREADS, 1)
lienet_kernel(const float* __restrict__ src, const float* __restrict__ Wg,
              const float* __restrict__ bg, const float* __restrict__ gg,
              const float* __restrict__ bb, float* __restrict__ out)
{
    extern __shared__ float sm[];
    unsigned* smu = reinterpret_cast<unsigned*>(sm);
    const int tid  = threadIdx.x;
    const int lane = tid & 31;
    const int w    = tid >> 5;
    const int base = blockIdx.x * MT;

    // ---- phase 0: LN params + bias to smem ----
    for (int j = tid; j < 1024; j += THREADS) {
        sm[OFF_SG + j]   = gg[j];
        sm[OFF_SB + j]   = bb[j];
        sm[OFF_BIAS + j] = bg[j];
    }
    // ---- context-row LN stats (prev row = token-32). Block 0: context is zeros. ----
    if (base != 0) {
        for (int rr = 0; rr < 2; rr++) {
            int r = w * 2 + rr;
            const float* p = src + (size_t)(base + r - B_DIM) * D_DIM;
            float s = 0.f, q = 0.f;
            for (int j = lane; j < D_DIM; j += 32) { float v = p[j]; s += v; q += v * v; }
            #pragma unroll
            for (int off = 16; off; off >>= 1) {
                s += __shfl_xor_sync(0xffffffffu, s, off);
                q += __shfl_xor_sync(0xffffffffu, q, off);
            }
            if (lane == 0) {
                float mu  = s * (1.f / D_DIM);
                float var = q * (1.f / D_DIM) - mu * mu;
                sm[OFF_MU + r] = mu;
                sm[OFF_RS + r] = rsqrtf(var + LN_EPS);
            }
        }
    }
    __syncthreads();

    const int g  = lane >> 2;   // 0..7
    const int q4 = lane & 3;    // 0..3
    const int wn = w & 7;       // 8 N-slices of 8 cols
    const int wm = w >> 3;      // 2 M-stripes of 16 rows
    const int r0 = wm * 16;
    const int n0 = wn * 8;

    for (int h = 0; h < H_DIM; h++) {
        // ---- stage A tile [32,128] as packed fp16 hi/lo pairs along k ----
        #pragma unroll
        for (int s = tid; s < MT * 64; s += THREADS) {
            int r = s >> 6, k2 = s & 63;
            float v0, v1;
            if (k2 < 32) {          // context half: cat cols 0..63 = LN(prev)
                if (base == 0) { v0 = 0.f; v1 = 0.f; }
                else {
                    int col = h * HD + 2 * k2;
                    float2 xv = *reinterpret_cast<const float2*>(
                        src + (size_t)(base + r - B_DIM) * D_DIM + col);
                    float mu = sm[OFF_MU + r], rs = sm[OFF_RS + r];
                    v0 = (xv.x - mu) * rs * sm[OFF_SG + col]     + sm[OFF_SB + col];
                    v1 = (xv.y - mu) * rs * sm[OFF_SG + col + 1] + sm[OFF_SB + col + 1];
                }
            } else {                // x half: cat cols 64..127 = src[token]
                int col = h * HD + 2 * (k2 - 32);
                float2 xv = *reinterpret_cast<const float2*>(
                    src + (size_t)(base + r) * D_DIM + col);
                v0 = xv.x; v1 = xv.y;
            }
            unsigned lo;
            unsigned hi = split_pack_hi(v0, v1, lo);
            smu[OFF_AHI + r * 68 + k2] = hi;
            smu[OFF_ALO + r * 68 + k2] = lo;
        }
        // ---- stage W_h [128,64] as packed fp16 hi/lo pairs along k ----
        #pragma unroll
        for (int s = tid; s < 64 * 64; s += THREADS) {
            int k2 = s >> 6, n = s & 63;
            const float* wp = Wg + (size_t)h * 8192 + (size_t)(2 * k2) * 64 + n;
            float v0 = wp[0], v1 = wp[64];
            unsigned lo;
            unsigned hi = split_pack_hi(v0, v1, lo);
            smu[OFF_WHI + k2 * 72 + n] = hi;
            smu[OFF_WLO + k2 * 72 + n] = lo;
        }
        __syncthreads();

        // ---- per-warp [16 x 8] output tile via 3-product fp16-split mma ----
        float acc[4] = {0.f, 0.f, 0.f, 0.f};
        #pragma unroll
        for (int kt = 0; kt < 8; kt++) {
            int kb = kt * 8;
            unsigned ah[4], al[4];
            ah[0] = smu[OFF_AHI + (r0 + g)     * 68 + kb + q4];
            ah[1] = smu[OFF_AHI + (r0 + g + 8) * 68 + kb + q4];
            ah[2] = smu[OFF_AHI + (r0 + g)     * 68 + kb + 4 + q4];
            ah[3] = smu[OFF_AHI + (r0 + g + 8) * 68 + kb + 4 + q4];
            al[0] = smu[OFF_ALO + (r0 + g)     * 68 + kb + q4];
            al[1] = smu[OFF_ALO + (r0 + g + 8) * 68 + kb + q4];
            al[2] = smu[OFF_ALO + (r0 + g)     * 68 + kb + 4 + q4];
            al[3] = smu[OFF_ALO + (r0 + g + 8) * 68 + kb + 4 + q4];
            unsigned bh0 = smu[OFF_WHI + (kb + q4)     * 72 + n0 + g];
            unsigned bh1 = smu[OFF_WHI + (kb + 4 + q4) * 72 + n0 + g];
            unsigned bl0 = smu[OFF_WLO + (kb + q4)     * 72 + n0 + g];
            unsigned bl1 = smu[OFF_WLO + (kb + 4 + q4) * 72 + n0 + g];
            mma16816(acc, ah, bh0, bh1);   // hi * hi
            mma16816(acc, ah, bl0, bl1);   // hi * lo
            mma16816(acc, al, bh0, bh1);   // lo * hi   (lo*lo ~ 2^-22, dropped)
        }
        // ---- epilogue: bias + exact GELU -> fp32 y tile in smem ----
        {
            int ncol = n0 + 2 * q4;
            int gcol = h * HD + ncol;
            float b0v = sm[OFF_BIAS + gcol], b1v = sm[OFF_BIAS + gcol + 1];
            float v00 = gelu_exact(acc[0] + b0v);
            float v01 = gelu_exact(acc[1] + b1v);
            float v10 = gelu_exact(acc[2] + b0v);
            float v11 = gelu_exact(acc[3] + b1v);
            *reinterpret_cast<float2*>(&sm[OFF_Y + (r0 + g)     * YSTRIDE + gcol]) = make_float2(v00, v01);
            *reinterpret_cast<float2*>(&sm[OFF_Y + (r0 + g + 8) * YSTRIDE + gcol]) = make_float2(v10, v11);
        }
        __syncthreads();
    }

    // ---- final LayerNorm over y rows + store ----
    for (int rr = 0; rr < 2; rr++) {
        int r = w * 2 + rr;
        float s = 0.f, q = 0.f;
        for (int j = lane; j < D_DIM; j += 32) {
            float v = sm[OFF_Y + r * YSTRIDE + j];
            s += v; q += v * v;
        }
        #pragma unroll
        for (int off = 16; off; off >>= 1) {
            s += __shfl_xor_sync(0xffffffffu, s, off);
            q += __shfl_xor_sync(0xffffffffu, q, off);
        }
        float mu = s * (1.f / D_DIM);
        float rs = rsqrtf(q * (1.f / D_DIM) - mu * mu + LN_EPS);
        float* op = out + (size_t)(base + r) * D_DIM;
        for (int j = lane; j < D_DIM; j += 32) {
            op[j] = (sm[OFF_Y + r * YSTRIDE + j] - mu) * rs * sm[OFF_SG + j] + sm[OFF_SB + j];
        }
    }
}

extern "C" void kernel_launch(void* const* d_in, const int* in_sizes, int n_in,
                              void* d_out, int out_size)
{
    const float* src   = (const float*)d_in[0];
    const float* W     = (const float*)d_in[1];
    const float* b     = (const float*)d_in[2];
    const float* gamma = (const float*)d_in[3];
    const float* beta  = (const float*)d_in[4];
    float* out = (float*)d_out;

    const size_t smem = (size_t)SMEM_WORDS * sizeof(float);  // ~194 KB
    cudaFuncSetAttribute((const void*)lienet_kernel,
                         cudaFuncAttributeMaxDynamicSharedMemorySize, (int)smem);
    lienet_kernel<<<NTOK / MT, THREADS, smem>>>(src, W, b, gamma, beta, out);
}

// round 4
// speedup vs baseline: 1.2924x; 1.2924x over previous
#include <cuda_runtime.h>
#include <cuda_fp16.h>
#include <math.h>

#define S_DIM 2048
#define B_DIM 32
#define D_DIM 1024
#define H_DIM 16
#define HD 64
#define NTOK (S_DIM*B_DIM)
#define MT 32
#define THREADS 512
#define LN_EPS 1e-5f

// smem layout in 32-bit words
#define YSTRIDE 1032
#define OFF_SG   0
#define OFF_SB   (OFF_SG + 1024)
#define OFF_BIAS (OFF_SB + 1024)
#define OFF_MU   (OFF_BIAS + 1024)
#define OFF_RS   (OFF_MU + 32)
#define OFF_Y    (OFF_RS + 32)
#define OFF_A    (OFF_Y + 32*YSTRIDE)
// per A buffer: hi 32*68, lo 32*68 -> 4352 words; two buffers
#define ABUF_WORDS 4352
#define SMEM_WORDS (OFF_A + 2*ABUF_WORDS)

// W fragments packed in mma B-fragment order: [h][wn(8)][kt(8)][lane(32)] = uint4{bh0,bh1,bl0,bl1}
__device__ uint4 g_Wfrag[H_DIM * 8 * 8 * 32];

__device__ __forceinline__ void mma16816(float* d, const unsigned* a, unsigned b0, unsigned b1) {
    asm volatile(
        "mma.sync.aligned.m16n8k16.row.col.f32.f16.f16.f32 "
        "{%0,%1,%2,%3}, {%4,%5,%6,%7}, {%8,%9}, {%0,%1,%2,%3};\n"
        : "+f"(d[0]), "+f"(d[1]), "+f"(d[2]), "+f"(d[3])
        : "r"(a[0]), "r"(a[1]), "r"(a[2]), "r"(a[3]), "r"(b0), "r"(b1));
}

__device__ __forceinline__ void ldsm_x4(unsigned& r0, unsigned& r1, unsigned& r2, unsigned& r3,
                                        unsigned saddr) {
    asm volatile("ldmatrix.sync.aligned.m8n8.x4.shared.b16 {%0,%1,%2,%3}, [%4];\n"
                 : "=r"(r0), "=r"(r1), "=r"(r2), "=r"(r3) : "r"(saddr));
}

__device__ __forceinline__ unsigned split_pack_hi(float v0, float v1, unsigned& lo_out) {
    __half h0 = __float2half_rn(v0), h1 = __float2half_rn(v1);
    __half l0 = __float2half_rn(v0 - __half2float(h0));
    __half l1 = __float2half_rn(v1 - __half2float(h1));
    lo_out = (unsigned)__half_as_ushort(l0) | ((unsigned)__half_as_ushort(l1) << 16);
    return (unsigned)__half_as_ushort(h0) | ((unsigned)__half_as_ushort(h1) << 16);
}

__device__ __forceinline__ float gelu_exact(float v) {
    return 0.5f * v * (1.0f + erff(v * 0.70710678118654752f));
}

// ---- prep: pack W into fragment-ordered hi/lo fp16 pairs (runs once per launch) ----
__global__ void pack_w_kernel(const float* __restrict__ Wg) {
    int idx = blockIdx.x * 256 + threadIdx.x;   // 0..32767
    int lane = idx & 31;
    int kt   = (idx >> 5) & 7;
    int wn   = (idx >> 8) & 7;
    int h    = idx >> 11;
    int g  = lane >> 2;
    int q4 = lane & 3;
    int n  = wn * 8 + g;
    int k0 = kt * 16 + q4 * 2;
    const float* wp = Wg + (size_t)h * 8192 + n;   // W[h][k][n], k-stride 64
    float v00 = wp[(size_t)k0 * 64],       v01 = wp[(size_t)(k0 + 1) * 64];
    float v10 = wp[(size_t)(k0 + 8) * 64], v11 = wp[(size_t)(k0 + 9) * 64];
    unsigned l0, l1;
    unsigned h0 = split_pack_hi(v00, v01, l0);
    unsigned h1 = split_pack_hi(v10, v11, l1);
    g_Wfrag[idx] = make_uint4(h0, h1, l0, l1);
}

__global__ void __launch_bounds__(THREADS, 1)
lienet_kernel(const float* __restrict__ src,
              const float* __restrict__ bg, const float* __restrict__ gg,
              const float* __restrict__ bb, float* __restrict__ out)
{
    extern __shared__ float sm[];
    unsigned* smu = reinterpret_cast<unsigned*>(sm);
    const int tid  = threadIdx.x;
    const int lane = tid & 31;
    const int w    = tid >> 5;
    const int base = blockIdx.x * MT;

    unsigned sbase;
    asm("{.reg .u64 t; cvta.to.shared.u64 t, %1; cvt.u32.u64 %0, t;}" : "=r"(sbase) : "l"(sm));

    // ---- phase 0: LN params + bias to smem ----
    for (int j = tid; j < 1024; j += THREADS) {
        sm[OFF_SG + j]   = gg[j];
        sm[OFF_SB + j]   = bb[j];
        sm[OFF_BIAS + j] = bg[j];
    }
    // ---- context-row LN stats (prev row = token-32). Block 0: context is zeros. ----
    if (base != 0) {
        for (int rr = 0; rr < 2; rr++) {
            int r = w * 2 + rr;
            const float* p = src + (size_t)(base + r - B_DIM) * D_DIM;
            float s = 0.f, q = 0.f;
            for (int j = lane; j < D_DIM; j += 32) { float v = p[j]; s += v; q += v * v; }
            #pragma unroll
            for (int off = 16; off; off >>= 1) {
                s += __shfl_xor_sync(0xffffffffu, s, off);
                q += __shfl_xor_sync(0xffffffffu, q, off);
            }
            if (lane == 0) {
                float mu  = s * (1.f / D_DIM);
                float var = q * (1.f / D_DIM) - mu * mu;
                sm[OFF_MU + r] = mu;
                sm[OFF_RS + r] = rsqrtf(var + LN_EPS);
            }
        }
    }
    __syncthreads();

    const int g  = lane >> 2;   // 0..7
    const int q4 = lane & 3;    // 0..3
    const int wn = w & 7;       // 8 N-slices of 8 cols
    const int wm = w >> 3;      // 2 M-stripes of 16 rows
    const int r0 = wm * 16;
    const int n0 = wn * 8;

    // per-lane ldmatrix.x4 byte addresses within an A buffer (row = lane&15, colgroup = lane>>4)
    const unsigned lds_row_off =
        ((unsigned)(r0 + (lane & 15)) * 68u + ((unsigned)(lane >> 4) << 2)) * 4u;
    const unsigned addrA = sbase + (unsigned)OFF_A * 4u + lds_row_off;

    for (int h = 0; h < H_DIM; h++) {
        const int par = h & 1;
        // ---- prefetch B fragments for this head (8 x LDG.128, L2 broadcast) ----
        const uint4* bp = g_Wfrag + ((size_t)(h * 8 + wn) * 8) * 32 + lane;
        uint4 bf[8];
        #pragma unroll
        for (int kt = 0; kt < 8; kt++) bf[kt] = bp[kt * 32];

        // ---- stage A tile [32,128] as packed fp16 hi/lo pairs along k ----
        const int abase = OFF_A + par * ABUF_WORDS;
        #pragma unroll
        for (int s = tid; s < MT * 64; s += THREADS) {
            int r = s >> 6, k2 = s & 63;
            float v0, v1;
            if (k2 < 32) {          // context half: cat cols 0..63 = LN(prev)
                if (base == 0) { v0 = 0.f; v1 = 0.f; }
                else {
                    int col = h * HD + 2 * k2;
                    float2 xv = *reinterpret_cast<const float2*>(
                        src + (size_t)(base + r - B_DIM) * D_DIM + col);
                    float mu = sm[OFF_MU + r], rs = sm[OFF_RS + r];
                    v0 = (xv.x - mu) * rs * sm[OFF_SG + col]     + sm[OFF_SB + col];
                    v1 = (xv.y - mu) * rs * sm[OFF_SG + col + 1] + sm[OFF_SB + col + 1];
                }
            } else {                // x half: cat cols 64..127 = src[token]
                int col = h * HD + 2 * (k2 - 32);
                float2 xv = *reinterpret_cast<const float2*>(
                    src + (size_t)(base + r) * D_DIM + col);
                v0 = xv.x; v1 = xv.y;
            }
            unsigned lo;
            unsigned hi = split_pack_hi(v0, v1, lo);
            smu[abase + r * 68 + k2]        = hi;   // hi plane
            smu[abase + 2176 + r * 68 + k2] = lo;   // lo plane
        }
        __syncthreads();

        // ---- per-warp [16 x 8] tile: 3-product fp16-split mma, 3 indep acc chains ----
        float accHH[4] = {0.f, 0.f, 0.f, 0.f};
        float accHL[4] = {0.f, 0.f, 0.f, 0.f};
        float accLH[4] = {0.f, 0.f, 0.f, 0.f};
        const unsigned ahAddr = addrA + (unsigned)(par * ABUF_WORDS) * 4u;
        const unsigned alAddr = ahAddr + 2176u * 4u;
        #pragma unroll
        for (int kt = 0; kt < 8; kt++) {
            unsigned ah[4], al[4];
            ldsm_x4(ah[0], ah[1], ah[2], ah[3], ahAddr + kt * 32u);
            ldsm_x4(al[0], al[1], al[2], al[3], alAddr + kt * 32u);
            mma16816(accHH, ah, bf[kt].x, bf[kt].y);   // hi * hi
            mma16816(accHL, ah, bf[kt].z, bf[kt].w);   // hi * lo
            mma16816(accLH, al, bf[kt].x, bf[kt].y);   // lo * hi  (lo*lo dropped)
        }

        // ---- epilogue: bias + exact GELU -> fp32 y tile in smem ----
        {
            int ncol = n0 + 2 * q4;
            int gcol = h * HD + ncol;
            float b0v = sm[OFF_BIAS + gcol], b1v = sm[OFF_BIAS + gcol + 1];
            float v00 = gelu_exact(accHH[0] + accHL[0] + accLH[0] + b0v);
            float v01 = gelu_exact(accHH[1] + accHL[1] + accLH[1] + b1v);
            float v10 = gelu_exact(accHH[2] + accHL[2] + accLH[2] + b0v);
            float v11 = gelu_exact(accHH[3] + accHL[3] + accLH[3] + b1v);
            *reinterpret_cast<float2*>(&sm[OFF_Y + (r0 + g)     * YSTRIDE + gcol]) = make_float2(v00, v01);
            *reinterpret_cast<float2*>(&sm[OFF_Y + (r0 + g + 8) * YSTRIDE + gcol]) = make_float2(v10, v11);
        }
        // no sync here: next head stages the OTHER A buffer; the barrier inside head h+1
        // orders all reads of buffer par(h) before the h+2 restaging of that buffer.
    }
    __syncthreads();   // all Y writes visible before final LN

    // ---- final LayerNorm over y rows + store ----
    for (int rr = 0; rr < 2; rr++) {
        int r = w * 2 + rr;
        float s = 0.f, q = 0.f;
        for (int j = lane; j < D_DIM; j += 32) {
            float v = sm[OFF_Y + r * YSTRIDE + j];
            s += v; q += v * v;
        }
        #pragma unroll
        for (int off = 16; off; off >>= 1) {
            s += __shfl_xor_sync(0xffffffffu, s, off);
            q += __shfl_xor_sync(0xffffffffu, q, off);
        }
        float mu = s * (1.f / D_DIM);
        float rs = rsqrtf(q * (1.f / D_DIM) - mu * mu + LN_EPS);
        float* op = out + (size_t)(base + r) * D_DIM;
        for (int j = lane; j < D_DIM; j += 32) {
            op[j] = (sm[OFF_Y + r * YSTRIDE + j] - mu) * rs * sm[OFF_SG + j] + sm[OFF_SB + j];
        }
    }
}

extern "C" void kernel_launch(void* const* d_in, const int* in_sizes, int n_in,
                              void* d_out, int out_size)
{
    const float* src   = (const float*)d_in[0];
    const float* W     = (const float*)d_in[1];
    const float* b     = (const float*)d_in[2];
    const float* gamma = (const float*)d_in[3];
    const float* beta  = (const float*)d_in[4];
    float* out = (float*)d_out;

    pack_w_kernel<<<128, 256>>>(W);

    const size_t smem = (size_t)SMEM_WORDS * sizeof(float);  // ~180 KB
    cudaFuncSetAttribute((const void*)lienet_kernel,
                         cudaFuncAttributeMaxDynamicSharedMemorySize, (int)smem);
    lienet_kernel<<<NTOK / MT, THREADS, smem>>>(src, b, gamma, beta, out);
}

// round 5
// speedup vs baseline: 1.6869x; 1.3053x over previous
#include <cuda_runtime.h>
#include <cuda_fp16.h>
#include <math.h>

#define S_DIM 2048
#define B_DIM 32
#define D_DIM 1024
#define H_DIM 16
#define NTOK (S_DIM*B_DIM)
#define MT 32
#define THREADS 512
#define LN_EPS 1e-5f

// smem layout (32-bit words)
#define YSTRIDE 1032
#define OFF_SG   0
#define OFF_SB   1024
#define OFF_BIAS 2048
#define OFF_MU   3072
#define OFF_RS   3104
#define OFF_Y    3136
#define OFF_A    (OFF_Y + 32*YSTRIDE)          // 36160
#define HBUF_WORDS 4352                         // per head: hi 32*68 + lo 32*68
#define SHBUF_WORDS (2*HBUF_WORDS)              // per superhead (2 heads)
#define SMEM_WORDS (OFF_A + 2*SHBUF_WORDS)      // 53568 words = 214 KB

// W fragments in mma B-fragment order: [h][slice8(8)][kt(8)][lane(32)] = uint4{bh0,bh1,bl0,bl1}
__device__ uint4 g_Wfrag[H_DIM * 8 * 8 * 32];

__device__ __forceinline__ void mma16816(float* d, const unsigned* a, unsigned b0, unsigned b1) {
    asm volatile(
        "mma.sync.aligned.m16n8k16.row.col.f32.f16.f16.f32 "
        "{%0,%1,%2,%3}, {%4,%5,%6,%7}, {%8,%9}, {%0,%1,%2,%3};\n"
        : "+f"(d[0]), "+f"(d[1]), "+f"(d[2]), "+f"(d[3])
        : "r"(a[0]), "r"(a[1]), "r"(a[2]), "r"(a[3]), "r"(b0), "r"(b1));
}
__device__ __forceinline__ void ldsm_x4(unsigned& r0, unsigned& r1, unsigned& r2, unsigned& r3,
                                        unsigned saddr) {
    asm volatile("ldmatrix.sync.aligned.m8n8.x4.shared.b16 {%0,%1,%2,%3}, [%4];\n"
                 : "=r"(r0), "=r"(r1), "=r"(r2), "=r"(r3) : "r"(saddr));
}
__device__ __forceinline__ void split2(float v0, float v1, unsigned& hi, unsigned& lo) {
    __half2 h2 = __float22half2_rn(make_float2(v0, v1));          // 1 cvt, packed
    float2 back = __half22float2(h2);
    __half2 l2 = __float22half2_rn(make_float2(v0 - back.x, v1 - back.y));
    hi = *reinterpret_cast<unsigned*>(&h2);
    lo = *reinterpret_cast<unsigned*>(&l2);
}
__device__ __forceinline__ float gelu_exact(float v) {
    return 0.5f * v * (1.0f + erff(v * 0.70710678118654752f));
}

__global__ void pack_w_kernel(const float* __restrict__ Wg) {
    int idx = blockIdx.x * 256 + threadIdx.x;   // 0..32767
    int lane = idx & 31;
    int kt   = (idx >> 5) & 7;
    int sl   = (idx >> 8) & 7;
    int h    = idx >> 11;
    int g  = lane >> 2;
    int q4 = lane & 3;
    int n  = sl * 8 + g;
    int k0 = kt * 16 + q4 * 2;
    const float* wp = Wg + (size_t)h * 8192 + n;   // W[h][k][n], k-stride 64
    unsigned h0, l0, h1, l1;
    split2(wp[(size_t)k0 * 64],       wp[(size_t)(k0 + 1) * 64], h0, l0);
    split2(wp[(size_t)(k0 + 8) * 64], wp[(size_t)(k0 + 9) * 64], h1, l1);
    g_Wfrag[idx] = make_uint4(h0, h1, l0, l1);
}

__global__ void __launch_bounds__(THREADS, 1)
lienet_kernel(const float* __restrict__ src,
              const float* __restrict__ bg, const float* __restrict__ gg,
              const float* __restrict__ bb, float* __restrict__ out)
{
    extern __shared__ float sm[];
    unsigned* smu = reinterpret_cast<unsigned*>(sm);
    const int tid  = threadIdx.x;
    const int lane = tid & 31;
    const int w    = tid >> 5;
    const int base = blockIdx.x * MT;

    unsigned sbase;
    asm("{.reg .u64 t; cvta.to.shared.u64 t, %1; cvt.u32.u64 %0, t;}" : "=r"(sbase) : "l"(sm));

    // ---- LN params + bias ----
    for (int j = tid; j < 1024; j += THREADS) {
        sm[OFF_SG + j]   = gg[j];
        sm[OFF_SB + j]   = bb[j];
        sm[OFF_BIAS + j] = bg[j];
    }
    // ---- context-row LN stats ----
    if (base != 0) {
        for (int rr = 0; rr < 2; rr++) {
            int r = w * 2 + rr;
            const float* p = src + (size_t)(base + r - B_DIM) * D_DIM;
            float s = 0.f, q = 0.f;
            for (int j = lane; j < D_DIM; j += 32) { float v = p[j]; s += v; q += v * v; }
            #pragma unroll
            for (int off = 16; off; off >>= 1) {
                s += __shfl_xor_sync(0xffffffffu, s, off);
                q += __shfl_xor_sync(0xffffffffu, q, off);
            }
            if (lane == 0) {
                float mu  = s * (1.f / D_DIM);
                sm[OFF_MU + r] = mu;
                sm[OFF_RS + r] = rsqrtf(q * (1.f / D_DIM) - mu * mu + LN_EPS);
            }
        }
    }
    __syncthreads();

    // ---- staging decomposition (fixed per thread) ----
    const int k2     = tid & 63;                 // word-pair col within cat(128)
    const bool isctx = (k2 < 32);
    const int rb     = tid >> 6;                 // row base 0..7 (+8*(i&3))

    // ---- mma warp mapping: hh = which head of the pair; 8 warps per head, 16x16 tiles ----
    const int g   = lane >> 2;
    const int q4  = lane & 3;
    const int hh  = w >> 3;                      // 0/1
    const int wm  = (w >> 2) & 1;                // 2 M stripes
    const int wn  = w & 3;                       // 4 N slices of 16
    const int r0  = wm * 16;

    const unsigned addrA0 = sbase + (unsigned)(OFF_A + hh * HBUF_WORDS) * 4u
        + ((unsigned)(r0 + (lane & 15)) * 68u + ((unsigned)(lane >> 4) << 2)) * 4u;

    float2 pre[8];
    // ---- preload superhead 0 ----
    #pragma unroll
    for (int i = 0; i < 8; i++) {
        int r = rb + (i & 3) * 8;
        int h = (i >> 2);                        // 2*hp + hh with hp=0
        if (isctx) {
            if (base == 0) pre[i] = make_float2(0.f, 0.f);
            else pre[i] = *reinterpret_cast<const float2*>(
                src + (size_t)(base + r - B_DIM) * D_DIM + h * 64 + 2 * k2);
        } else {
            pre[i] = *reinterpret_cast<const float2*>(
                src + (size_t)(base + r) * D_DIM + h * 64 + 2 * (k2 - 32));
        }
    }

    for (int hp = 0; hp < 8; hp++) {
        const int par = hp & 1;
        const int abase0 = OFF_A + par * SHBUF_WORDS;

        // ---- store staged A (both heads of pair) ----
        #pragma unroll
        for (int i = 0; i < 8; i++) {
            int r = rb + (i & 3) * 8;
            int hloc = (i >> 2);                 // head-in-pair
            int h = 2 * hp + hloc;
            float v0, v1;
            if (isctx) {
                if (base == 0) { v0 = 0.f; v1 = 0.f; }
                else {
                    int col = h * 64 + 2 * k2;
                    float mu = sm[OFF_MU + r], rs = sm[OFF_RS + r];
                    v0 = (pre[i].x - mu) * rs * sm[OFF_SG + col]     + sm[OFF_SB + col];
                    v1 = (pre[i].y - mu) * rs * sm[OFF_SG + col + 1] + sm[OFF_SB + col + 1];
                }
            } else { v0 = pre[i].x; v1 = pre[i].y; }
            unsigned hi, lo;
            split2(v0, v1, hi, lo);
            int abase = abase0 + hloc * HBUF_WORDS;
            smu[abase + r * 68 + k2]        = hi;
            smu[abase + 2176 + r * 68 + k2] = lo;
        }

        // ---- issue B loads (first half) before barrier ----
        const int h = 2 * hp + hh;
        const uint4* bp0 = g_Wfrag + ((size_t)(h * 8 + 2 * wn) * 8) * 32 + lane;
        const uint4* bp1 = bp0 + 256;            // next 8-col slice
        uint4 b0a[4], b1a[4];
        #pragma unroll
        for (int kt = 0; kt < 4; kt++) { b0a[kt] = bp0[kt * 32]; b1a[kt] = bp1[kt * 32]; }

        __syncthreads();

        // ---- prefetch next superhead src into regs (covered by mma below) ----
        if (hp < 7) {
            #pragma unroll
            for (int i = 0; i < 8; i++) {
                int r = rb + (i & 3) * 8;
                int hn = 2 * (hp + 1) + (i >> 2);
                if (isctx) {
                    if (base == 0) pre[i] = make_float2(0.f, 0.f);
                    else pre[i] = *reinterpret_cast<const float2*>(
                        src + (size_t)(base + r - B_DIM) * D_DIM + hn * 64 + 2 * k2);
                } else {
                    pre[i] = *reinterpret_cast<const float2*>(
                        src + (size_t)(base + r) * D_DIM + hn * 64 + 2 * (k2 - 32));
                }
            }
        }

        // ---- mma: 16x16 per warp, 3-product fp16 split ----
        float aHH0[4] = {0,0,0,0}, aHL0[4] = {0,0,0,0}, aLH0[4] = {0,0,0,0};
        float aHH1[4] = {0,0,0,0}, aHL1[4] = {0,0,0,0}, aLH1[4] = {0,0,0,0};
        const unsigned ahAddr = addrA0 + (unsigned)(par * SHBUF_WORDS) * 4u;
        const unsigned alAddr = ahAddr + 2176u * 4u;
        #pragma unroll
        for (int kt = 0; kt < 4; kt++) {
            unsigned ah[4], al[4];
            ldsm_x4(ah[0], ah[1], ah[2], ah[3], ahAddr + kt * 32u);
            ldsm_x4(al[0], al[1], al[2], al[3], alAddr + kt * 32u);
            mma16816(aHH0, ah, b0a[kt].x, b0a[kt].y);
            mma16816(aHL0, ah, b0a[kt].z, b0a[kt].w);
            mma16816(aLH0, al, b0a[kt].x, b0a[kt].y);
            mma16816(aHH1, ah, b1a[kt].x, b1a[kt].y);
            mma16816(aHL1, ah, b1a[kt].z, b1a[kt].w);
            mma16816(aLH1, al, b1a[kt].x, b1a[kt].y);
        }
        #pragma unroll
        for (int kt = 0; kt < 4; kt++) { b0a[kt] = bp0[(kt + 4) * 32]; b1a[kt] = bp1[(kt + 4) * 32]; }
        #pragma unroll
        for (int kt = 0; kt < 4; kt++) {
            unsigned ah[4], al[4];
            ldsm_x4(ah[0], ah[1], ah[2], ah[3], ahAddr + (kt + 4) * 32u);
            ldsm_x4(al[0], al[1], al[2], al[3], alAddr + (kt + 4) * 32u);
            mma16816(aHH0, ah, b0a[kt].x, b0a[kt].y);
            mma16816(aHL0, ah, b0a[kt].z, b0a[kt].w);
            mma16816(aLH0, al, b0a[kt].x, b0a[kt].y);
            mma16816(aHH1, ah, b1a[kt].x, b1a[kt].y);
            mma16816(aHL1, ah, b1a[kt].z, b1a[kt].w);
            mma16816(aLH1, al, b1a[kt].x, b1a[kt].y);
        }

        // ---- epilogue: bias + GELU -> Y ----
        #pragma unroll
        for (int sub = 0; sub < 2; sub++) {
            const float* aHH = sub ? aHH1 : aHH0;
            const float* aHL = sub ? aHL1 : aHL0;
            const float* aLH = sub ? aLH1 : aLH0;
            int gcol = h * 64 + wn * 16 + sub * 8 + 2 * q4;
            float b0v = sm[OFF_BIAS + gcol], b1v = sm[OFF_BIAS + gcol + 1];
            float v00 = gelu_exact(aHH[0] + aHL[0] + aLH[0] + b0v);
            float v01 = gelu_exact(aHH[1] + aHL[1] + aLH[1] + b1v);
            float v10 = gelu_exact(aHH[2] + aHL[2] + aLH[2] + b0v);
            float v11 = gelu_exact(aHH[3] + aHL[3] + aLH[3] + b1v);
            *reinterpret_cast<float2*>(&sm[OFF_Y + (r0 + g)     * YSTRIDE + gcol]) = make_float2(v00, v01);
            *reinterpret_cast<float2*>(&sm[OFF_Y + (r0 + g + 8) * YSTRIDE + gcol]) = make_float2(v10, v11);
        }
        // double-buffered: barrier inside next iteration orders buffer reuse
    }
    __syncthreads();

    // ---- final LayerNorm ----
    for (int rr = 0; rr < 2; rr++) {
        int r = w * 2 + rr;
        float s = 0.f, q = 0.f;
        for (int j = lane; j < D_DIM; j += 32) {
            float v = sm[OFF_Y + r * YSTRIDE + j];
            s += v; q += v * v;
        }
        #pragma unroll
        for (int off = 16; off; off >>= 1) {
            s += __shfl_xor_sync(0xffffffffu, s, off);
            q += __shfl_xor_sync(0xffffffffu, q, off);
        }
        float mu = s * (1.f / D_DIM);
        float rs = rsqrtf(q * (1.f / D_DIM) - mu * mu + LN_EPS);
        float* op = out + (size_t)(base + r) * D_DIM;
        for (int j = lane; j < D_DIM; j += 32) {
            op[j] = (sm[OFF_Y + r * YSTRIDE + j] - mu) * rs * sm[OFF_SG + j] + sm[OFF_SB + j];
        }
    }
}

extern "C" void kernel_launch(void* const* d_in, const int* in_sizes, int n_in,
                              void* d_out, int out_size)
{
    const float* src   = (const float*)d_in[0];
    const float* W     = (const float*)d_in[1];
    const float* b     = (const float*)d_in[2];
    const float* gamma = (const float*)d_in[3];
    const float* beta  = (const float*)d_in[4];
    float* out = (float*)d_out;

    pack_w_kernel<<<128, 256>>>(W);

    const size_t smem = (size_t)SMEM_WORDS * sizeof(float);  // ~214 KB
    cudaFuncSetAttribute((const void*)lienet_kernel,
                         cudaFuncAttributeMaxDynamicSharedMemorySize, (int)smem);
    lienet_kernel<<<NTOK / MT, THREADS, smem>>>(src, b, gamma, beta, out);
}

// round 6
// speedup vs baseline: 1.9109x; 1.1328x over previous
#include <cuda_runtime.h>
#include <cuda_fp16.h>
#include <math.h>

#define S_DIM 2048
#define B_DIM 32
#define D_DIM 1024
#define H_DIM 16
#define NTOK (S_DIM*B_DIM)
#define MT 16
#define THREADS 256
#define LN_EPS 1e-5f

// smem layout (32-bit words)
#define YSTRIDE 1032
#define OFF_SG   0
#define OFF_SB   1024
#define OFF_BIAS 2048
#define OFF_MU   3072
#define OFF_RS   3088
#define OFF_Y    3104
#define OFF_A    (OFF_Y + MT*YSTRIDE)           // 19616
#define HBUF_WORDS 2176                          // per head: hi 16*68 + lo 16*68
#define SMEM_WORDS (OFF_A + 2*HBUF_WORDS)        // 23968 words = 95.9 KB

// W fragments in mma B-fragment order: [h][slice8(8)][kt(8)][lane(32)] = uint4{bh0,bh1,bl0,bl1}
__device__ uint4 g_Wfrag[H_DIM * 8 * 8 * 32];

__device__ __forceinline__ void mma16816(float* d, const unsigned* a, unsigned b0, unsigned b1) {
    asm volatile(
        "mma.sync.aligned.m16n8k16.row.col.f32.f16.f16.f32 "
        "{%0,%1,%2,%3}, {%4,%5,%6,%7}, {%8,%9}, {%0,%1,%2,%3};\n"
        : "+f"(d[0]), "+f"(d[1]), "+f"(d[2]), "+f"(d[3])
        : "r"(a[0]), "r"(a[1]), "r"(a[2]), "r"(a[3]), "r"(b0), "r"(b1));
}
__device__ __forceinline__ void ldsm_x4(unsigned& r0, unsigned& r1, unsigned& r2, unsigned& r3,
                                        unsigned saddr) {
    asm volatile("ldmatrix.sync.aligned.m8n8.x4.shared.b16 {%0,%1,%2,%3}, [%4];\n"
                 : "=r"(r0), "=r"(r1), "=r"(r2), "=r"(r3) : "r"(saddr));
}
__device__ __forceinline__ void split2(float v0, float v1, unsigned& hi, unsigned& lo) {
    __half2 h2 = __float22half2_rn(make_float2(v0, v1));
    float2 back = __half22float2(h2);
    __half2 l2 = __float22half2_rn(make_float2(v0 - back.x, v1 - back.y));
    hi = *reinterpret_cast<unsigned*>(&h2);
    lo = *reinterpret_cast<unsigned*>(&l2);
}
__device__ __forceinline__ float gelu_exact(float v) {
    return 0.5f * v * (1.0f + erff(v * 0.70710678118654752f));
}

__global__ void pack_w_kernel(const float* __restrict__ Wg) {
    int idx = blockIdx.x * 256 + threadIdx.x;   // 0..32767
    int lane = idx & 31;
    int kt   = (idx >> 5) & 7;
    int sl   = (idx >> 8) & 7;
    int h    = idx >> 11;
    int g  = lane >> 2;
    int q4 = lane & 3;
    int n  = sl * 8 + g;
    int k0 = kt * 16 + q4 * 2;
    const float* wp = Wg + (size_t)h * 8192 + n;   // W[h][k][n], k-stride 64
    unsigned h0, l0, h1, l1;
    split2(wp[(size_t)k0 * 64],       wp[(size_t)(k0 + 1) * 64], h0, l0);
    split2(wp[(size_t)(k0 + 8) * 64], wp[(size_t)(k0 + 9) * 64], h1, l1);
    g_Wfrag[idx] = make_uint4(h0, h1, l0, l1);
}

__global__ void __launch_bounds__(THREADS, 2)
lienet_kernel(const float* __restrict__ src,
              const float* __restrict__ bg, const float* __restrict__ gg,
              const float* __restrict__ bb, float* __restrict__ out)
{
    extern __shared__ float sm[];
    unsigned* smu = reinterpret_cast<unsigned*>(sm);
    const int tid  = threadIdx.x;
    const int lane = tid & 31;
    const int w    = tid >> 5;
    const int base = blockIdx.x * MT;
    const bool hasctx = (base >= B_DIM);         // first 32 tokens: context = zeros

    unsigned sbase;
    asm("{.reg .u64 t; cvta.to.shared.u64 t, %1; cvt.u32.u64 %0, t;}" : "=r"(sbase) : "l"(sm));

    // ---- LN params + bias ----
    for (int j = tid; j < 1024; j += THREADS) {
        sm[OFF_SG + j]   = gg[j];
        sm[OFF_SB + j]   = bb[j];
        sm[OFF_BIAS + j] = bg[j];
    }
    // ---- context-row LN stats: 8 warps x 2 rows ----
    if (hasctx) {
        for (int rr = 0; rr < 2; rr++) {
            int r = w * 2 + rr;
            const float* p = src + (size_t)(base + r - B_DIM) * D_DIM;
            float s = 0.f, q = 0.f;
            for (int j = lane; j < D_DIM; j += 32) { float v = p[j]; s += v; q += v * v; }
            #pragma unroll
            for (int off = 16; off; off >>= 1) {
                s += __shfl_xor_sync(0xffffffffu, s, off);
                q += __shfl_xor_sync(0xffffffffu, q, off);
            }
            if (lane == 0) {
                float mu  = s * (1.f / D_DIM);
                sm[OFF_MU + r] = mu;
                sm[OFF_RS + r] = rsqrtf(q * (1.f / D_DIM) - mu * mu + LN_EPS);
            }
        }
    }
    __syncthreads();

    // ---- staging decomposition (fixed per thread): 8 (row,headloc) items ----
    const int k2     = tid & 63;                 // word-pair col within cat(128)
    const bool isctx = (k2 < 32);
    const int rb     = tid >> 6;                 // row base 0..3 (+4 per item)

    // ---- mma warp mapping: 2 heads x 4 n-slices(16 cols); each warp m16n16 ----
    const int g   = lane >> 2;
    const int q4  = lane & 3;
    const int hh  = w >> 2;                      // head-in-pair 0/1
    const int wn  = w & 3;                       // n-slice of 16 cols

    const unsigned ahAddr = sbase + (unsigned)(OFF_A + hh * HBUF_WORDS) * 4u
        + ((unsigned)(lane & 15) * 68u + ((unsigned)(lane >> 4) << 2)) * 4u;
    const unsigned alAddr = ahAddr + 1088u * 4u;

    float2 pre[8];
    // ---- preload superhead 0 ----
    #pragma unroll
    for (int i = 0; i < 8; i++) {
        int r = rb + (i & 3) * 4;
        int h = (i >> 2);
        if (isctx) {
            if (!hasctx) pre[i] = make_float2(0.f, 0.f);
            else pre[i] = *reinterpret_cast<const float2*>(
                src + (size_t)(base + r - B_DIM) * D_DIM + h * 64 + 2 * k2);
        } else {
            pre[i] = *reinterpret_cast<const float2*>(
                src + (size_t)(base + r) * D_DIM + h * 64 + 2 * (k2 - 32));
        }
    }

    for (int hp = 0; hp < 8; hp++) {
        // ---- stage A (both heads of pair, single buffer) ----
        #pragma unroll
        for (int i = 0; i < 8; i++) {
            int r = rb + (i & 3) * 4;
            int hloc = i >> 2;
            int h = 2 * hp + hloc;
            float v0, v1;
            if (isctx) {
                if (!hasctx) { v0 = 0.f; v1 = 0.f; }
                else {
                    int col = h * 64 + 2 * k2;
                    float mu = sm[OFF_MU + r], rs = sm[OFF_RS + r];
                    v0 = (pre[i].x - mu) * rs * sm[OFF_SG + col]     + sm[OFF_SB + col];
                    v1 = (pre[i].y - mu) * rs * sm[OFF_SG + col + 1] + sm[OFF_SB + col + 1];
                }
            } else { v0 = pre[i].x; v1 = pre[i].y; }
            unsigned hi, lo;
            split2(v0, v1, hi, lo);
            int abase = OFF_A + hloc * HBUF_WORDS;
            smu[abase + r * 68 + k2]        = hi;
            smu[abase + 1088 + r * 68 + k2] = lo;
        }

        // ---- issue B loads (first half) before barrier ----
        const int h = 2 * hp + hh;
        const uint4* bp0 = g_Wfrag + ((size_t)(h * 8 + 2 * wn) * 8) * 32 + lane;
        const uint4* bp1 = bp0 + 256;
        uint4 b0a[4], b1a[4];
        #pragma unroll
        for (int kt = 0; kt < 4; kt++) { b0a[kt] = bp0[kt * 32]; b1a[kt] = bp1[kt * 32]; }

        __syncthreads();                          // staging done -> mma may read

        // ---- prefetch next superhead src (covered by mma latency) ----
        if (hp < 7) {
            #pragma unroll
            for (int i = 0; i < 8; i++) {
                int r = rb + (i & 3) * 4;
                int hn = 2 * (hp + 1) + (i >> 2);
                if (isctx) {
                    if (!hasctx) pre[i] = make_float2(0.f, 0.f);
                    else pre[i] = *reinterpret_cast<const float2*>(
                        src + (size_t)(base + r - B_DIM) * D_DIM + hn * 64 + 2 * k2);
                } else {
                    pre[i] = *reinterpret_cast<const float2*>(
                        src + (size_t)(base + r) * D_DIM + hn * 64 + 2 * (k2 - 32));
                }
            }
        }

        // ---- mma: m16n16 per warp, folded 2-chain fp16 split ----
        float aHH0[4] = {0,0,0,0}, aX0[4] = {0,0,0,0};
        float aHH1[4] = {0,0,0,0}, aX1[4] = {0,0,0,0};
        #pragma unroll
        for (int kt = 0; kt < 4; kt++) {
            unsigned ah[4], al[4];
            ldsm_x4(ah[0], ah[1], ah[2], ah[3], ahAddr + kt * 32u);
            ldsm_x4(al[0], al[1], al[2], al[3], alAddr + kt * 32u);
            mma16816(aHH0, ah, b0a[kt].x, b0a[kt].y);
            mma16816(aX0,  ah, b0a[kt].z, b0a[kt].w);
            mma16816(aX0,  al, b0a[kt].x, b0a[kt].y);
            mma16816(aHH1, ah, b1a[kt].x, b1a[kt].y);
            mma16816(aX1,  ah, b1a[kt].z, b1a[kt].w);
            mma16816(aX1,  al, b1a[kt].x, b1a[kt].y);
        }
        #pragma unroll
        for (int kt = 0; kt < 4; kt++) { b0a[kt] = bp0[(kt + 4) * 32]; b1a[kt] = bp1[(kt + 4) * 32]; }
        #pragma unroll
        for (int kt = 0; kt < 4; kt++) {
            unsigned ah[4], al[4];
            ldsm_x4(ah[0], ah[1], ah[2], ah[3], ahAddr + (kt + 4) * 32u);
            ldsm_x4(al[0], al[1], al[2], al[3], alAddr + (kt + 4) * 32u);
            mma16816(aHH0, ah, b0a[kt].x, b0a[kt].y);
            mma16816(aX0,  ah, b0a[kt].z, b0a[kt].w);
            mma16816(aX0,  al, b0a[kt].x, b0a[kt].y);
            mma16816(aHH1, ah, b1a[kt].x, b1a[kt].y);
            mma16816(aX1,  ah, b1a[kt].z, b1a[kt].w);
            mma16816(aX1,  al, b1a[kt].x, b1a[kt].y);
        }

        // ---- epilogue: bias + GELU -> Y ----
        #pragma unroll
        for (int sub = 0; sub < 2; sub++) {
            const float* aHH = sub ? aHH1 : aHH0;
            const float* aX  = sub ? aX1  : aX0;
            int gcol = h * 64 + wn * 16 + sub * 8 + 2 * q4;
            float b0v = sm[OFF_BIAS + gcol], b1v = sm[OFF_BIAS + gcol + 1];
            float v00 = gelu_exact(aHH[0] + aX[0] + b0v);
            float v01 = gelu_exact(aHH[1] + aX[1] + b1v);
            float v10 = gelu_exact(aHH[2] + aX[2] + b0v);
            float v11 = gelu_exact(aHH[3] + aX[3] + b1v);
            *reinterpret_cast<float2*>(&sm[OFF_Y + g       * YSTRIDE + gcol]) = make_float2(v00, v01);
            *reinterpret_cast<float2*>(&sm[OFF_Y + (g + 8) * YSTRIDE + gcol]) = make_float2(v10, v11);
        }
        __syncthreads();                          // A-buffer reads done -> next stage may write
    }

    // ---- final LayerNorm: 8 warps x 2 rows ----
    for (int rr = 0; rr < 2; rr++) {
        int r = w * 2 + rr;
        float s = 0.f, q = 0.f;
        for (int j = lane; j < D_DIM; j += 32) {
            float v = sm[OFF_Y + r * YSTRIDE + j];
            s += v; q += v * v;
        }
        #pragma unroll
        for (int off = 16; off; off >>= 1) {
            s += __shfl_xor_sync(0xffffffffu, s, off);
            q += __shfl_xor_sync(0xffffffffu, q, off);
        }
        float mu = s * (1.f / D_DIM);
        float rs = rsqrtf(q * (1.f / D_DIM) - mu * mu + LN_EPS);
        float* op = out + (size_t)(base + r) * D_DIM;
        for (int j = lane; j < D_DIM; j += 32) {
            op[j] = (sm[OFF_Y + r * YSTRIDE + j] - mu) * rs * sm[OFF_SG + j] + sm[OFF_SB + j];
        }
    }
}

extern "C" void kernel_launch(void* const* d_in, const int* in_sizes, int n_in,
                              void* d_out, int out_size)
{
    const float* src   = (const float*)d_in[0];
    const float* W     = (const float*)d_in[1];
    const float* b     = (const float*)d_in[2];
    const float* gamma = (const float*)d_in[3];
    const float* beta  = (const float*)d_in[4];
    float* out = (float*)d_out;

    pack_w_kernel<<<128, 256>>>(W);

    const size_t smem = (size_t)SMEM_WORDS * sizeof(float);  // 95.9 KB -> 2 CTAs/SM
    cudaFuncSetAttribute((const void*)lienet_kernel,
                         cudaFuncAttributeMaxDynamicSharedMemorySize, (int)smem);
    lienet_kernel<<<NTOK / MT, THREADS, smem>>>(src, b, gamma, beta, out);
}

// round 7
// speedup vs baseline: 2.0989x; 1.0984x over previous
#include <cuda_runtime.h>
#include <cuda_fp16.h>
#include <math.h>

#define S_DIM 2048
#define B_DIM 32
#define D_DIM 1024
#define H_DIM 16
#define NTOK (S_DIM*B_DIM)
#define MT 16
#define THREADS 256
#define LN_EPS 1e-5f

// smem layout (32-bit words)
#define YSTRIDE 1032
#define OFF_SG   0
#define OFF_SB   1024
#define OFF_BIAS 2048
#define OFF_MU   3072
#define OFF_RS   3088
#define OFF_Y    3104
#define OFF_A    (OFF_Y + MT*YSTRIDE)           // 19616
#define HBUF_WORDS 1088                          // per head: hi plane only, 16*68
#define SMEM_WORDS (OFF_A + 2*HBUF_WORDS)        // 21792 words = 87.2 KB

// W fragments in mma B-fragment order: [h][slice8(8)][kt(8)][lane(32)] = uint4{bh0,bh1,bl0,bl1}
__device__ uint4 g_Wfrag[H_DIM * 8 * 8 * 32];

__device__ __forceinline__ void mma16816(float* d, const unsigned* a, unsigned b0, unsigned b1) {
    asm volatile(
        "mma.sync.aligned.m16n8k16.row.col.f32.f16.f16.f32 "
        "{%0,%1,%2,%3}, {%4,%5,%6,%7}, {%8,%9}, {%0,%1,%2,%3};\n"
        : "+f"(d[0]), "+f"(d[1]), "+f"(d[2]), "+f"(d[3])
        : "r"(a[0]), "r"(a[1]), "r"(a[2]), "r"(a[3]), "r"(b0), "r"(b1));
}
__device__ __forceinline__ void ldsm_x4(unsigned& r0, unsigned& r1, unsigned& r2, unsigned& r3,
                                        unsigned saddr) {
    asm volatile("ldmatrix.sync.aligned.m8n8.x4.shared.b16 {%0,%1,%2,%3}, [%4];\n"
                 : "=r"(r0), "=r"(r1), "=r"(r2), "=r"(r3) : "r"(saddr));
}
__device__ __forceinline__ void split2(float v0, float v1, unsigned& hi, unsigned& lo) {
    __half2 h2 = __float22half2_rn(make_float2(v0, v1));
    float2 back = __half22float2(h2);
    __half2 l2 = __float22half2_rn(make_float2(v0 - back.x, v1 - back.y));
    hi = *reinterpret_cast<unsigned*>(&h2);
    lo = *reinterpret_cast<unsigned*>(&l2);
}
__device__ __forceinline__ unsigned pack_h2(float v0, float v1) {
    __half2 h2 = __float22half2_rn(make_float2(v0, v1));
    return *reinterpret_cast<unsigned*>(&h2);
}
__device__ __forceinline__ float gelu_exact(float v) {
    return 0.5f * v * (1.0f + erff(v * 0.70710678118654752f));
}

__global__ void pack_w_kernel(const float* __restrict__ Wg) {
    int idx = blockIdx.x * 256 + threadIdx.x;   // 0..32767
    int lane = idx & 31;
    int kt   = (idx >> 5) & 7;
    int sl   = (idx >> 8) & 7;
    int h    = idx >> 11;
    int g  = lane >> 2;
    int q4 = lane & 3;
    int n  = sl * 8 + g;
    int k0 = kt * 16 + q4 * 2;
    const float* wp = Wg + (size_t)h * 8192 + n;   // W[h][k][n], k-stride 64
    unsigned h0, l0, h1, l1;
    split2(wp[(size_t)k0 * 64],       wp[(size_t)(k0 + 1) * 64], h0, l0);
    split2(wp[(size_t)(k0 + 8) * 64], wp[(size_t)(k0 + 9) * 64], h1, l1);
    g_Wfrag[idx] = make_uint4(h0, h1, l0, l1);
}

__global__ void __launch_bounds__(THREADS, 2)
lienet_kernel(const float* __restrict__ src,
              const float* __restrict__ bg, const float* __restrict__ gg,
              const float* __restrict__ bb, float* __restrict__ out)
{
    extern __shared__ float sm[];
    unsigned* smu = reinterpret_cast<unsigned*>(sm);
    const int tid  = threadIdx.x;
    const int lane = tid & 31;
    const int w    = tid >> 5;
    const int base = blockIdx.x * MT;
    const bool hasctx = (base >= B_DIM);         // first 32 tokens: context = zeros

    unsigned sbase;
    asm("{.reg .u64 t; cvta.to.shared.u64 t, %1; cvt.u32.u64 %0, t;}" : "=r"(sbase) : "l"(sm));

    // ---- LN params + bias ----
    for (int j = tid; j < 1024; j += THREADS) {
        sm[OFF_SG + j]   = gg[j];
        sm[OFF_SB + j]   = bb[j];
        sm[OFF_BIAS + j] = bg[j];
    }
    // ---- context-row LN stats: 8 warps x 2 rows ----
    if (hasctx) {
        for (int rr = 0; rr < 2; rr++) {
            int r = w * 2 + rr;
            const float* p = src + (size_t)(base + r - B_DIM) * D_DIM;
            float s = 0.f, q = 0.f;
            for (int j = lane; j < D_DIM; j += 32) { float v = p[j]; s += v; q += v * v; }
            #pragma unroll
            for (int off = 16; off; off >>= 1) {
                s += __shfl_xor_sync(0xffffffffu, s, off);
                q += __shfl_xor_sync(0xffffffffu, q, off);
            }
            if (lane == 0) {
                float mu  = s * (1.f / D_DIM);
                sm[OFF_MU + r] = mu;
                sm[OFF_RS + r] = rsqrtf(q * (1.f / D_DIM) - mu * mu + LN_EPS);
            }
        }
    }
    __syncthreads();

    // ---- staging decomposition (fixed per thread): 8 (row,headloc) items ----
    const int k2     = tid & 63;                 // word-pair col within cat(128)
    const bool isctx = (k2 < 32);
    const int rb     = tid >> 6;                 // row base 0..3 (+4 per item)

    // ---- mma warp mapping: 2 heads x 4 n-slices(16 cols); each warp m16n16 ----
    const int g   = lane >> 2;
    const int q4  = lane & 3;
    const int hh  = w >> 2;                      // head-in-pair 0/1
    const int wn  = w & 3;                       // n-slice of 16 cols

    const unsigned ahAddr = sbase + (unsigned)(OFF_A + hh * HBUF_WORDS) * 4u
        + ((unsigned)(lane & 15) * 68u + ((unsigned)(lane >> 4) << 2)) * 4u;

    float2 pre[8];
    // ---- preload superhead 0 ----
    #pragma unroll
    for (int i = 0; i < 8; i++) {
        int r = rb + (i & 3) * 4;
        int h = (i >> 2);
        if (isctx) {
            if (!hasctx) pre[i] = make_float2(0.f, 0.f);
            else pre[i] = *reinterpret_cast<const float2*>(
                src + (size_t)(base + r - B_DIM) * D_DIM + h * 64 + 2 * k2);
        } else {
            pre[i] = *reinterpret_cast<const float2*>(
                src + (size_t)(base + r) * D_DIM + h * 64 + 2 * (k2 - 32));
        }
    }

    for (int hp = 0; hp < 8; hp++) {
        // ---- stage A hi-plane (both heads of pair) ----
        #pragma unroll
        for (int i = 0; i < 8; i++) {
            int r = rb + (i & 3) * 4;
            int hloc = i >> 2;
            int h = 2 * hp + hloc;
            float v0, v1;
            if (isctx) {
                if (!hasctx) { v0 = 0.f; v1 = 0.f; }
                else {
                    int col = h * 64 + 2 * k2;
                    float mu = sm[OFF_MU + r], rs = sm[OFF_RS + r];
                    v0 = (pre[i].x - mu) * rs * sm[OFF_SG + col]     + sm[OFF_SB + col];
                    v1 = (pre[i].y - mu) * rs * sm[OFF_SG + col + 1] + sm[OFF_SB + col + 1];
                }
            } else { v0 = pre[i].x; v1 = pre[i].y; }
            smu[OFF_A + hloc * HBUF_WORDS + r * 68 + k2] = pack_h2(v0, v1);
        }

        // ---- issue B loads (first half) before barrier ----
        const int h = 2 * hp + hh;
        const uint4* bp0 = g_Wfrag + ((size_t)(h * 8 + 2 * wn) * 8) * 32 + lane;
        const uint4* bp1 = bp0 + 256;
        uint4 b0a[4], b1a[4];
        #pragma unroll
        for (int kt = 0; kt < 4; kt++) { b0a[kt] = bp0[kt * 32]; b1a[kt] = bp1[kt * 32]; }

        __syncthreads();                          // staging done -> mma may read

        // ---- prefetch next superhead src (covered by mma latency) ----
        if (hp < 7) {
            #pragma unroll
            for (int i = 0; i < 8; i++) {
                int r = rb + (i & 3) * 4;
                int hn = 2 * (hp + 1) + (i >> 2);
                if (isctx) {
                    if (!hasctx) pre[i] = make_float2(0.f, 0.f);
                    else pre[i] = *reinterpret_cast<const float2*>(
                        src + (size_t)(base + r - B_DIM) * D_DIM + hn * 64 + 2 * k2);
                } else {
                    pre[i] = *reinterpret_cast<const float2*>(
                        src + (size_t)(base + r) * D_DIM + hn * 64 + 2 * (k2 - 32));
                }
            }
        }

        // ---- mma: m16n16 per warp; A fp16, W hi+lo (2 chains) ----
        float aHH0[4] = {0,0,0,0}, aX0[4] = {0,0,0,0};
        float aHH1[4] = {0,0,0,0}, aX1[4] = {0,0,0,0};
        #pragma unroll
        for (int kt = 0; kt < 4; kt++) {
            unsigned ah[4];
            ldsm_x4(ah[0], ah[1], ah[2], ah[3], ahAddr + kt * 32u);
            mma16816(aHH0, ah, b0a[kt].x, b0a[kt].y);
            mma16816(aX0,  ah, b0a[kt].z, b0a[kt].w);
            mma16816(aHH1, ah, b1a[kt].x, b1a[kt].y);
            mma16816(aX1,  ah, b1a[kt].z, b1a[kt].w);
        }
        #pragma unroll
        for (int kt = 0; kt < 4; kt++) { b0a[kt] = bp0[(kt + 4) * 32]; b1a[kt] = bp1[(kt + 4) * 32]; }
        #pragma unroll
        for (int kt = 0; kt < 4; kt++) {
            unsigned ah[4];
            ldsm_x4(ah[0], ah[1], ah[2], ah[3], ahAddr + (kt + 4) * 32u);
            mma16816(aHH0, ah, b0a[kt].x, b0a[kt].y);
            mma16816(aX0,  ah, b0a[kt].z, b0a[kt].w);
            mma16816(aHH1, ah, b1a[kt].x, b1a[kt].y);
            mma16816(aX1,  ah, b1a[kt].z, b1a[kt].w);
        }

        // ---- epilogue: bias + GELU -> Y ----
        #pragma unroll
        for (int sub = 0; sub < 2; sub++) {
            const float* aHH = sub ? aHH1 : aHH0;
            const float* aX  = sub ? aX1  : aX0;
            int gcol = h * 64 + wn * 16 + sub * 8 + 2 * q4;
            float b0v = sm[OFF_BIAS + gcol], b1v = sm[OFF_BIAS + gcol + 1];
            float v00 = gelu_exact(aHH[0] + aX[0] + b0v);
            float v01 = gelu_exact(aHH[1] + aX[1] + b1v);
            float v10 = gelu_exact(aHH[2] + aX[2] + b0v);
            float v11 = gelu_exact(aHH[3] + aX[3] + b1v);
            *reinterpret_cast<float2*>(&sm[OFF_Y + g       * YSTRIDE + gcol]) = make_float2(v00, v01);
            *reinterpret_cast<float2*>(&sm[OFF_Y + (g + 8) * YSTRIDE + gcol]) = make_float2(v10, v11);
        }
        __syncthreads();                          // A-buffer reads done -> next stage may write
    }

    // ---- final LayerNorm: 8 warps x 2 rows ----
    for (int rr = 0; rr < 2; rr++) {
        int r = w * 2 + rr;
        float s = 0.f, q = 0.f;
        for (int j = lane; j < D_DIM; j += 32) {
            float v = sm[OFF_Y + r * YSTRIDE + j];
            s += v; q += v * v;
        }
        #pragma unroll
        for (int off = 16; off; off >>= 1) {
            s += __shfl_xor_sync(0xffffffffu, s, off);
            q += __shfl_xor_sync(0xffffffffu, q, off);
        }
        float mu = s * (1.f / D_DIM);
        float rs = rsqrtf(q * (1.f / D_DIM) - mu * mu + LN_EPS);
        float* op = out + (size_t)(base + r) * D_DIM;
        for (int j = lane; j < D_DIM; j += 32) {
            op[j] = (sm[OFF_Y + r * YSTRIDE + j] - mu) * rs * sm[OFF_SG + j] + sm[OFF_SB + j];
        }
    }
}

extern "C" void kernel_launch(void* const* d_in, const int* in_sizes, int n_in,
                              void* d_out, int out_size)
{
    const float* src   = (const float*)d_in[0];
    const float* W     = (const float*)d_in[1];
    const float* b     = (const float*)d_in[2];
    const float* gamma = (const float*)d_in[3];
    const float* beta  = (const float*)d_in[4];
    float* out = (float*)d_out;

    pack_w_kernel<<<128, 256>>>(W);

    const size_t smem = (size_t)SMEM_WORDS * sizeof(float);  // 87.2 KB -> 2 CTAs/SM
    cudaFuncSetAttribute((const void*)lienet_kernel,
                         cudaFuncAttributeMaxDynamicSharedMemorySize, (int)smem);
    lienet_kernel<<<NTOK / MT, THREADS, smem>>>(src, b, gamma, beta, out);
}

// round 9
// speedup vs baseline: 2.6201x; 1.2483x over previous
#include <cuda_runtime.h>
#include <cuda_fp16.h>
#include <math.h>

#define S_DIM 2048
#define B_DIM 32
#define D_DIM 1024
#define H_DIM 16
#define NTOK (S_DIM*B_DIM)
#define MT 16
#define THREADS 256
#define LN_EPS 1e-5f

// smem layout (32-bit words)
#define YSTRIDE 1032
#define OFF_SG   0
#define OFF_SB   1024
#define OFF_BIAS 2048
#define OFF_MU   3072
#define OFF_RS   3088
#define OFF_Y    3104
#define OFF_A    (OFF_Y + MT*YSTRIDE)           // 19616
#define HBUF_WORDS 1088                          // per head: 16 rows * 68
#define ABUF_WORDS (4*HBUF_WORDS)                // 4 heads per iteration
#define SMEM_WORDS (OFF_A + 2*ABUF_WORDS)        // 28320 words = 110.6 KiB

// W fragments (fp16 only) in mma B order:
// [h][sl(8)][ktp(4)][lane(32)] = uint4{ b0(kt=2p), b1(kt=2p), b0(kt=2p+1), b1(kt=2p+1) }
__device__ uint4 g_W2[H_DIM * 8 * 4 * 32];       // 256 KB

__device__ __forceinline__ void mma16816(float* d, const unsigned* a, unsigned b0, unsigned b1) {
    asm volatile(
        "mma.sync.aligned.m16n8k16.row.col.f32.f16.f16.f32 "
        "{%0,%1,%2,%3}, {%4,%5,%6,%7}, {%8,%9}, {%0,%1,%2,%3};\n"
        : "+f"(d[0]), "+f"(d[1]), "+f"(d[2]), "+f"(d[3])
        : "r"(a[0]), "r"(a[1]), "r"(a[2]), "r"(a[3]), "r"(b0), "r"(b1));
}
__device__ __forceinline__ void ldsm_x4(unsigned& r0, unsigned& r1, unsigned& r2, unsigned& r3,
                                        unsigned saddr) {
    asm volatile("ldmatrix.sync.aligned.m8n8.x4.shared.b16 {%0,%1,%2,%3}, [%4];\n"
                 : "=r"(r0), "=r"(r1), "=r"(r2), "=r"(r3) : "r"(saddr));
}
__device__ __forceinline__ unsigned pack_h2(float v0, float v1) {
    __half2 h2 = __float22half2_rn(make_float2(v0, v1));
    return *reinterpret_cast<unsigned*>(&h2);
}
__device__ __forceinline__ float gelu_exact(float v) {
    return 0.5f * v * (1.0f + erff(v * 0.70710678118654752f));
}

__global__ void pack_w_kernel(const float* __restrict__ Wg) {
    int idx = blockIdx.x * 256 + threadIdx.x;   // 0..16383
    int lane = idx & 31;
    int ktp  = (idx >> 5) & 3;
    int sl   = (idx >> 7) & 7;
    int h    = idx >> 10;
    int g  = lane >> 2;
    int q4 = lane & 3;
    int n  = sl * 8 + g;
    const float* wp = Wg + (size_t)h * 8192 + n;   // W[h][k][n], k-stride 64
    int ka = (2 * ktp) * 16 + q4 * 2;               // even kt
    int kb = ka + 16;                               // odd kt
    unsigned b0a = pack_h2(wp[(size_t)ka * 64],       wp[(size_t)(ka + 1) * 64]);
    unsigned b1a = pack_h2(wp[(size_t)(ka + 8) * 64], wp[(size_t)(ka + 9) * 64]);
    unsigned b0b = pack_h2(wp[(size_t)kb * 64],       wp[(size_t)(kb + 1) * 64]);
    unsigned b1b = pack_h2(wp[(size_t)(kb + 8) * 64], wp[(size_t)(kb + 9) * 64]);
    g_W2[idx] = make_uint4(b0a, b1a, b0b, b1b);
}

__global__ void __launch_bounds__(THREADS, 2)
lienet_kernel(const float* __restrict__ src,
              const float* __restrict__ bg, const float* __restrict__ gg,
              const float* __restrict__ bb, float* __restrict__ out)
{
    extern __shared__ float sm[];
    unsigned* smu = reinterpret_cast<unsigned*>(sm);
    const int tid  = threadIdx.x;
    const int lane = tid & 31;
    const int w    = tid >> 5;
    const int base = blockIdx.x * MT;
    const bool hasctx = (base >= B_DIM);

    unsigned sbase;
    asm("{.reg .u64 t; cvta.to.shared.u64 t, %1; cvt.u32.u64 %0, t;}" : "=r"(sbase) : "l"(sm));

    // ---- LN params + bias ----
    for (int j = tid; j < 1024; j += THREADS) {
        sm[OFF_SG + j]   = gg[j];
        sm[OFF_SB + j]   = bb[j];
        sm[OFF_BIAS + j] = bg[j];
    }
    // ---- context-row LN stats: 8 warps x 2 rows ----
    if (hasctx) {
        for (int rr = 0; rr < 2; rr++) {
            int r = w * 2 + rr;
            const float* p = src + (size_t)(base + r - B_DIM) * D_DIM;
            float s = 0.f, q = 0.f;
            for (int j = lane; j < D_DIM; j += 32) { float v = p[j]; s += v; q += v * v; }
            #pragma unroll
            for (int off = 16; off; off >>= 1) {
                s += __shfl_xor_sync(0xffffffffu, s, off);
                q += __shfl_xor_sync(0xffffffffu, q, off);
            }
            if (lane == 0) {
                float mu  = s * (1.f / D_DIM);
                sm[OFF_MU + r] = mu;
                sm[OFF_RS + r] = rsqrtf(q * (1.f / D_DIM) - mu * mu + LN_EPS);
            }
        }
    }
    __syncthreads();

    // ---- staging decomposition: 16 items = 4 heads x 4 row-groups ----
    const int k2     = tid & 63;
    const bool isctx = (k2 < 32);
    const int rb     = tid >> 6;                 // row base 0..3

    // ---- mma warp mapping: head hh = w>>1 (4 heads/iter), n-half nh = w&1 (32 cols) ----
    const int g   = lane >> 2;
    const int q4  = lane & 3;
    const int hh  = w >> 1;
    const int nh  = w & 1;

    const unsigned ahBase = sbase + (unsigned)(OFF_A + hh * HBUF_WORDS) * 4u
        + ((unsigned)(lane & 15) * 68u + ((unsigned)(lane >> 4) << 2)) * 4u;

    float2 pre[16];
    // ---- preload iter 0 (heads 0..3) ----
    #pragma unroll
    for (int i = 0; i < 16; i++) {
        int r = rb + (i & 3) * 4;
        int h = i >> 2;
        if (isctx) {
            if (!hasctx) pre[i] = make_float2(0.f, 0.f);
            else pre[i] = *reinterpret_cast<const float2*>(
                src + (size_t)(base + r - B_DIM) * D_DIM + h * 64 + 2 * k2);
        } else {
            pre[i] = *reinterpret_cast<const float2*>(
                src + (size_t)(base + r) * D_DIM + h * 64 + 2 * (k2 - 32));
        }
    }

    for (int it = 0; it < 4; it++) {
        const int buf = it & 1;
        // ---- stage A fp16 (4 heads) ----
        #pragma unroll
        for (int i = 0; i < 16; i++) {
            int r = rb + (i & 3) * 4;
            int hloc = i >> 2;
            int h = 4 * it + hloc;
            float v0, v1;
            if (isctx) {
                if (!hasctx) { v0 = 0.f; v1 = 0.f; }
                else {
                    int col = h * 64 + 2 * k2;
                    float mu = sm[OFF_MU + r], rs = sm[OFF_RS + r];
                    v0 = (pre[i].x - mu) * rs * sm[OFF_SG + col]     + sm[OFF_SB + col];
                    v1 = (pre[i].y - mu) * rs * sm[OFF_SG + col + 1] + sm[OFF_SB + col + 1];
                }
            } else { v0 = pre[i].x; v1 = pre[i].y; }
            smu[OFF_A + buf * ABUF_WORDS + hloc * HBUF_WORDS + r * 68 + k2] = pack_h2(v0, v1);
        }

        // ---- issue B loads (ktp 0,1 for 4 slices) before barrier ----
        const int h = 4 * it + hh;
        const uint4* bwp = g_W2 + (size_t)((h * 8 + nh * 4) * 4) * 32 + lane;
        uint4 bq[8];
        #pragma unroll
        for (int sl = 0; sl < 4; sl++) {
            bq[sl * 2 + 0] = bwp[(sl * 4 + 0) * 32];
            bq[sl * 2 + 1] = bwp[(sl * 4 + 1) * 32];
        }

        __syncthreads();                          // A[buf] ready

        // ---- prefetch next iteration's src (covered by mma) ----
        if (it < 3) {
            #pragma unroll
            for (int i = 0; i < 16; i++) {
                int r = rb + (i & 3) * 4;
                int hn = 4 * (it + 1) + (i >> 2);
                if (isctx) {
                    if (!hasctx) pre[i] = make_float2(0.f, 0.f);
                    else pre[i] = *reinterpret_cast<const float2*>(
                        src + (size_t)(base + r - B_DIM) * D_DIM + hn * 64 + 2 * k2);
                } else {
                    pre[i] = *reinterpret_cast<const float2*>(
                        src + (size_t)(base + r) * D_DIM + hn * 64 + 2 * (k2 - 32));
                }
            }
        }

        // ---- mma: m16 n32 k128 per warp, single fp16 chain ----
        float acc[4][4] = {{0,0,0,0},{0,0,0,0},{0,0,0,0},{0,0,0,0}};
        const unsigned ahAddr = ahBase + (unsigned)(buf * ABUF_WORDS) * 4u;
        #pragma unroll
        for (int kt = 0; kt < 4; kt++) {
            unsigned ah[4];
            ldsm_x4(ah[0], ah[1], ah[2], ah[3], ahAddr + kt * 32u);
            #pragma unroll
            for (int sl = 0; sl < 4; sl++) {
                const uint4& f = bq[sl * 2 + (kt >> 1)];
                if (kt & 1) mma16816(acc[sl], ah, f.z, f.w);
                else        mma16816(acc[sl], ah, f.x, f.y);
            }
        }
        #pragma unroll
        for (int sl = 0; sl < 4; sl++) {
            bq[sl * 2 + 0] = bwp[(sl * 4 + 2) * 32];
            bq[sl * 2 + 1] = bwp[(sl * 4 + 3) * 32];
        }
        #pragma unroll
        for (int kt = 4; kt < 8; kt++) {
            unsigned ah[4];
            ldsm_x4(ah[0], ah[1], ah[2], ah[3], ahAddr + kt * 32u);
            #pragma unroll
            for (int sl = 0; sl < 4; sl++) {
                const uint4& f = bq[sl * 2 + ((kt - 4) >> 1)];
                if (kt & 1) mma16816(acc[sl], ah, f.z, f.w);
                else        mma16816(acc[sl], ah, f.x, f.y);
            }
        }

        // ---- epilogue: bias + GELU -> Y ----
        #pragma unroll
        for (int sl = 0; sl < 4; sl++) {
            int gcol = h * 64 + nh * 32 + sl * 8 + 2 * q4;
            float b0v = sm[OFF_BIAS + gcol], b1v = sm[OFF_BIAS + gcol + 1];
            float v00 = gelu_exact(acc[sl][0] + b0v);
            float v01 = gelu_exact(acc[sl][1] + b1v);
            float v10 = gelu_exact(acc[sl][2] + b0v);
            float v11 = gelu_exact(acc[sl][3] + b1v);
            *reinterpret_cast<float2*>(&sm[OFF_Y + g       * YSTRIDE + gcol]) = make_float2(v00, v01);
            *reinterpret_cast<float2*>(&sm[OFF_Y + (g + 8) * YSTRIDE + gcol]) = make_float2(v10, v11);
        }
        // single barrier per iteration: next iteration's barrier orders buffer reuse
    }
    __syncthreads();

    // ---- final LayerNorm: 8 warps x 2 rows ----
    for (int rr = 0; rr < 2; rr++) {
        int r = w * 2 + rr;
        float s = 0.f, q = 0.f;
        for (int j = lane; j < D_DIM; j += 32) {
            float v = sm[OFF_Y + r * YSTRIDE + j];
            s += v; q += v * v;
        }
        #pragma unroll
        for (int off = 16; off; off >>= 1) {
            s += __shfl_xor_sync(0xffffffffu, s, off);
            q += __shfl_xor_sync(0xffffffffu, q, off);
        }
        float mu = s * (1.f / D_DIM);
        float rs = rsqrtf(q * (1.f / D_DIM) - mu * mu + LN_EPS);
        float* op = out + (size_t)(base + r) * D_DIM;
        for (int j = lane; j < D_DIM; j += 32) {
            op[j] = (sm[OFF_Y + r * YSTRIDE + j] - mu) * rs * sm[OFF_SG + j] + sm[OFF_SB + j];
        }
    }
}

extern "C" void kernel_launch(void* const* d_in, const int* in_sizes, int n_in,
                              void* d_out, int out_size)
{
    const float* src   = (const float*)d_in[0];
    const float* W     = (const float*)d_in[1];
    const float* b     = (const float*)d_in[2];
    const float* gamma = (const float*)d_in[3];
    const float* beta  = (const float*)d_in[4];
    float* out = (float*)d_out;

    pack_w_kernel<<<64, 256>>>(W);

    const size_t smem = (size_t)SMEM_WORDS * sizeof(float);  // 110.6 KiB -> 2 CTAs/SM
    cudaFuncSetAttribute((const void*)lienet_kernel,
                         cudaFuncAttributeMaxDynamicSharedMemorySize, (int)smem);
    lienet_kernel<<<NTOK / MT, THREADS, smem>>>(src, b, gamma, beta, out);
}

// round 10
// speedup vs baseline: 2.6554x; 1.0135x over previous
#include <cuda_runtime.h>
#include <cuda_fp16.h>
#include <math.h>

#define S_DIM 2048
#define B_DIM 32
#define D_DIM 1024
#define H_DIM 16
#define NTOK (S_DIM*B_DIM)
#define MT 16
#define THREADS 256
#define LN_EPS 1e-5f

// smem layout (32-bit words)
#define OFF_SG   0
#define OFF_SB   1024
#define OFF_BIAS 2048
#define OFF_MU   3072
#define OFF_RS   3088
#define OFF_RED  3104                           // 16 rows x 8 warps x {s,q} = 256 words
#define OFF_A    3360                            // 16B aligned (13440 B)
#define HBUF_WORDS 1088                          // per head: 16 rows * 68
#define ABUF_WORDS (4*HBUF_WORDS)                // 4 heads per iteration
#define SMEM_WORDS (OFF_A + 2*ABUF_WORDS)        // 12064 words = 48.3 KiB

// W fragments (fp16) in mma B order:
// [h][sl(8)][ktp(4)][lane(32)] = uint4{ b0(kt=2p), b1(kt=2p), b0(kt=2p+1), b1(kt=2p+1) }
__device__ uint4 g_W2[H_DIM * 8 * 4 * 32];       // 256 KB

__device__ __forceinline__ void mma16816(float* d, const unsigned* a, unsigned b0, unsigned b1) {
    asm volatile(
        "mma.sync.aligned.m16n8k16.row.col.f32.f16.f16.f32 "
        "{%0,%1,%2,%3}, {%4,%5,%6,%7}, {%8,%9}, {%0,%1,%2,%3};\n"
        : "+f"(d[0]), "+f"(d[1]), "+f"(d[2]), "+f"(d[3])
        : "r"(a[0]), "r"(a[1]), "r"(a[2]), "r"(a[3]), "r"(b0), "r"(b1));
}
__device__ __forceinline__ void ldsm_x4(unsigned& r0, unsigned& r1, unsigned& r2, unsigned& r3,
                                        unsigned saddr) {
    asm volatile("ldmatrix.sync.aligned.m8n8.x4.shared.b16 {%0,%1,%2,%3}, [%4];\n"
                 : "=r"(r0), "=r"(r1), "=r"(r2), "=r"(r3) : "r"(saddr));
}
__device__ __forceinline__ unsigned pack_h2(float v0, float v1) {
    __half2 h2 = __float22half2_rn(make_float2(v0, v1));
    return *reinterpret_cast<unsigned*>(&h2);
}
__device__ __forceinline__ float2 unpack_h2(unsigned u) {
    __half2 h2 = *reinterpret_cast<__half2*>(&u);
    return __half22float2(h2);
}
__device__ __forceinline__ float gelu_exact(float v) {
    return 0.5f * v * (1.0f + erff(v * 0.70710678118654752f));
}

__global__ void pack_w_kernel(const float* __restrict__ Wg) {
    int idx = blockIdx.x * 256 + threadIdx.x;   // 0..16383
    int lane = idx & 31;
    int ktp  = (idx >> 5) & 3;
    int sl   = (idx >> 7) & 7;
    int h    = idx >> 10;
    int g  = lane >> 2;
    int q4 = lane & 3;
    int n  = sl * 8 + g;
    const float* wp = Wg + (size_t)h * 8192 + n;   // W[h][k][n], k-stride 64
    int ka = (2 * ktp) * 16 + q4 * 2;
    int kb = ka + 16;
    unsigned b0a = pack_h2(wp[(size_t)ka * 64],       wp[(size_t)(ka + 1) * 64]);
    unsigned b1a = pack_h2(wp[(size_t)(ka + 8) * 64], wp[(size_t)(ka + 9) * 64]);
    unsigned b0b = pack_h2(wp[(size_t)kb * 64],       wp[(size_t)(kb + 1) * 64]);
    unsigned b1b = pack_h2(wp[(size_t)(kb + 8) * 64], wp[(size_t)(kb + 9) * 64]);
    g_W2[idx] = make_uint4(b0a, b1a, b0b, b1b);
}

__global__ void __launch_bounds__(THREADS, 2)
lienet_kernel(const float* __restrict__ src,
              const float* __restrict__ bg, const float* __restrict__ gg,
              const float* __restrict__ bb, float* __restrict__ out)
{
    extern __shared__ float sm[];
    unsigned* smu = reinterpret_cast<unsigned*>(sm);
    const int tid  = threadIdx.x;
    const int lane = tid & 31;
    const int w    = tid >> 5;
    const int base = blockIdx.x * MT;
    const bool hasctx = (base >= B_DIM);

    unsigned sbase;
    asm("{.reg .u64 t; cvta.to.shared.u64 t, %1; cvt.u32.u64 %0, t;}" : "=r"(sbase) : "l"(sm));

    // ---- LN params + bias ----
    for (int j = tid; j < 1024; j += THREADS) {
        sm[OFF_SG + j]   = gg[j];
        sm[OFF_SB + j]   = bb[j];
        sm[OFF_BIAS + j] = bg[j];
    }
    // ---- context-row LN stats: 8 warps x 2 rows ----
    if (hasctx) {
        for (int rr = 0; rr < 2; rr++) {
            int r = w * 2 + rr;
            const float* p = src + (size_t)(base + r - B_DIM) * D_DIM;
            float s = 0.f, q = 0.f;
            for (int j = lane; j < D_DIM; j += 32) { float v = p[j]; s += v; q += v * v; }
            #pragma unroll
            for (int off = 16; off; off >>= 1) {
                s += __shfl_xor_sync(0xffffffffu, s, off);
                q += __shfl_xor_sync(0xffffffffu, q, off);
            }
            if (lane == 0) {
                float mu  = s * (1.f / D_DIM);
                sm[OFF_MU + r] = mu;
                sm[OFF_RS + r] = rsqrtf(q * (1.f / D_DIM) - mu * mu + LN_EPS);
            }
        }
    }
    __syncthreads();

    // ---- staging decomposition: 16 items = 4 heads x 4 row-groups ----
    const int k2     = tid & 63;
    const bool isctx = (k2 < 32);
    const int rb     = tid >> 6;                 // row base 0..3

    // ---- mma warp mapping: head hh = w>>1 (4 heads/iter), n-half nh = w&1 ----
    const int g   = lane >> 2;
    const int q4  = lane & 3;
    const int hh  = w >> 1;
    const int nh  = w & 1;

    const unsigned ahBase = sbase + (unsigned)(OFF_A + hh * HBUF_WORDS) * 4u
        + ((unsigned)(lane & 15) * 68u + ((unsigned)(lane >> 4) << 2)) * 4u;

    unsigned y2[32];                             // packed y: [(it*4+sl)*2 + p], p: 0=row g, 1=row g+8

    #pragma unroll
    for (int it = 0; it < 4; it++) {
        const int buf = it & 1;

        // ---- load src for 4 heads (16 independent LDG) ----
        float2 tmp[16];
        #pragma unroll
        for (int i = 0; i < 16; i++) {
            int r = rb + (i & 3) * 4;
            int h = 4 * it + (i >> 2);
            if (isctx) {
                if (!hasctx) tmp[i] = make_float2(0.f, 0.f);
                else tmp[i] = *reinterpret_cast<const float2*>(
                    src + (size_t)(base + r - B_DIM) * D_DIM + h * 64 + 2 * k2);
            } else {
                tmp[i] = *reinterpret_cast<const float2*>(
                    src + (size_t)(base + r) * D_DIM + h * 64 + 2 * (k2 - 32));
            }
        }
        // ---- transform + stage A fp16 ----
        #pragma unroll
        for (int i = 0; i < 16; i++) {
            int r = rb + (i & 3) * 4;
            int hloc = i >> 2;
            int h = 4 * it + hloc;
            float v0, v1;
            if (isctx && hasctx) {
                int col = h * 64 + 2 * k2;
                float mu = sm[OFF_MU + r], rs = sm[OFF_RS + r];
                v0 = (tmp[i].x - mu) * rs * sm[OFF_SG + col]     + sm[OFF_SB + col];
                v1 = (tmp[i].y - mu) * rs * sm[OFF_SG + col + 1] + sm[OFF_SB + col + 1];
            } else { v0 = tmp[i].x; v1 = tmp[i].y; }
            smu[OFF_A + buf * ABUF_WORDS + hloc * HBUF_WORDS + r * 68 + k2] = pack_h2(v0, v1);
        }

        // ---- B loads (first half) before barrier ----
        const int h = 4 * it + hh;
        const uint4* bwp = g_W2 + (size_t)((h * 8 + nh * 4) * 4) * 32 + lane;
        uint4 bq[8];
        #pragma unroll
        for (int sl = 0; sl < 4; sl++) {
            bq[sl * 2 + 0] = bwp[(sl * 4 + 0) * 32];
            bq[sl * 2 + 1] = bwp[(sl * 4 + 1) * 32];
        }

        __syncthreads();                          // A[buf] ready

        // ---- mma: m16 n32 k128 per warp ----
        float acc[4][4] = {{0,0,0,0},{0,0,0,0},{0,0,0,0},{0,0,0,0}};
        const unsigned ahAddr = ahBase + (unsigned)(buf * ABUF_WORDS) * 4u;
        #pragma unroll
        for (int kt = 0; kt < 4; kt++) {
            unsigned ah[4];
            ldsm_x4(ah[0], ah[1], ah[2], ah[3], ahAddr + kt * 32u);
            #pragma unroll
            for (int sl = 0; sl < 4; sl++) {
                const uint4& f = bq[sl * 2 + (kt >> 1)];
                if (kt & 1) mma16816(acc[sl], ah, f.z, f.w);
                else        mma16816(acc[sl], ah, f.x, f.y);
            }
        }
        #pragma unroll
        for (int sl = 0; sl < 4; sl++) {
            bq[sl * 2 + 0] = bwp[(sl * 4 + 2) * 32];
            bq[sl * 2 + 1] = bwp[(sl * 4 + 3) * 32];
        }
        #pragma unroll
        for (int kt = 4; kt < 8; kt++) {
            unsigned ah[4];
            ldsm_x4(ah[0], ah[1], ah[2], ah[3], ahAddr + kt * 32u);
            #pragma unroll
            for (int sl = 0; sl < 4; sl++) {
                const uint4& f = bq[sl * 2 + ((kt - 4) >> 1)];
                if (kt & 1) mma16816(acc[sl], ah, f.z, f.w);
                else        mma16816(acc[sl], ah, f.x, f.y);
            }
        }

        // ---- epilogue: bias + GELU -> packed y registers ----
        #pragma unroll
        for (int sl = 0; sl < 4; sl++) {
            int gcol = h * 64 + nh * 32 + sl * 8 + 2 * q4;
            float b0v = sm[OFF_BIAS + gcol], b1v = sm[OFF_BIAS + gcol + 1];
            float v00 = gelu_exact(acc[sl][0] + b0v);
            float v01 = gelu_exact(acc[sl][1] + b1v);
            float v10 = gelu_exact(acc[sl][2] + b0v);
            float v11 = gelu_exact(acc[sl][3] + b1v);
            y2[(it * 4 + sl) * 2 + 0] = pack_h2(v00, v01);   // row g
            y2[(it * 4 + sl) * 2 + 1] = pack_h2(v10, v11);   // row g+8
        }
        // next iteration's barrier orders A-buffer reuse
    }

    // ---- final LN: register reduction -> scratch -> normalize -> gmem ----
    float s0 = 0.f, q0 = 0.f, s1 = 0.f, q1 = 0.f;
    #pragma unroll
    for (int i = 0; i < 16; i++) {
        float2 v0 = unpack_h2(y2[2 * i]);
        float2 v1 = unpack_h2(y2[2 * i + 1]);
        s0 += v0.x + v0.y;  q0 += v0.x * v0.x + v0.y * v0.y;
        s1 += v1.x + v1.y;  q1 += v1.x * v1.x + v1.y * v1.y;
    }
    #pragma unroll
    for (int off = 1; off <= 2; off <<= 1) {     // reduce over q4 quad (same rows)
        s0 += __shfl_xor_sync(0xffffffffu, s0, off);
        q0 += __shfl_xor_sync(0xffffffffu, q0, off);
        s1 += __shfl_xor_sync(0xffffffffu, s1, off);
        q1 += __shfl_xor_sync(0xffffffffu, q1, off);
    }
    if (q4 == 0) {
        *reinterpret_cast<float2*>(&sm[OFF_RED + (g * 8 + w) * 2])       = make_float2(s0, q0);
        *reinterpret_cast<float2*>(&sm[OFF_RED + ((g + 8) * 8 + w) * 2]) = make_float2(s1, q1);
    }
    __syncthreads();
    float S0 = 0.f, Q0 = 0.f, S1 = 0.f, Q1 = 0.f;
    #pragma unroll
    for (int k = 0; k < 8; k++) {
        float2 a = *reinterpret_cast<const float2*>(&sm[OFF_RED + (g * 8 + k) * 2]);
        float2 b2 = *reinterpret_cast<const float2*>(&sm[OFF_RED + ((g + 8) * 8 + k) * 2]);
        S0 += a.x;  Q0 += a.y;
        S1 += b2.x; Q1 += b2.y;
    }
    const float mu0 = S0 * (1.f / D_DIM);
    const float rs0 = rsqrtf(Q0 * (1.f / D_DIM) - mu0 * mu0 + LN_EPS);
    const float mu1 = S1 * (1.f / D_DIM);
    const float rs1 = rsqrtf(Q1 * (1.f / D_DIM) - mu1 * mu1 + LN_EPS);

    float* op0 = out + (size_t)(base + g) * D_DIM;
    float* op1 = out + (size_t)(base + g + 8) * D_DIM;
    #pragma unroll
    for (int it = 0; it < 4; it++) {
        #pragma unroll
        for (int sl = 0; sl < 4; sl++) {
            int gcol = (4 * it + hh) * 64 + nh * 32 + sl * 8 + 2 * q4;
            float ga0 = sm[OFF_SG + gcol], ga1 = sm[OFF_SG + gcol + 1];
            float be0 = sm[OFF_SB + gcol], be1 = sm[OFF_SB + gcol + 1];
            float2 v0 = unpack_h2(y2[(it * 4 + sl) * 2 + 0]);
            float2 v1 = unpack_h2(y2[(it * 4 + sl) * 2 + 1]);
            *reinterpret_cast<float2*>(op0 + gcol) =
                make_float2((v0.x - mu0) * rs0 * ga0 + be0, (v0.y - mu0) * rs0 * ga1 + be1);
            *reinterpret_cast<float2*>(op1 + gcol) =
                make_float2((v1.x - mu1) * rs1 * ga0 + be0, (v1.y - mu1) * rs1 * ga1 + be1);
        }
    }
}

extern "C" void kernel_launch(void* const* d_in, const int* in_sizes, int n_in,
                              void* d_out, int out_size)
{
    const float* src   = (const float*)d_in[0];
    const float* W     = (const float*)d_in[1];
    const float* b     = (const float*)d_in[2];
    const float* gamma = (const float*)d_in[3];
    const float* beta  = (const float*)d_in[4];
    float* out = (float*)d_out;

    pack_w_kernel<<<64, 256>>>(W);

    const size_t smem = (size_t)SMEM_WORDS * sizeof(float);  // 48.3 KiB
    cudaFuncSetAttribute((const void*)lienet_kernel,
                         cudaFuncAttributeMaxDynamicSharedMemorySize, (int)smem);
    lienet_kernel<<<NTOK / MT, THREADS, smem>>>(src, b, gamma, beta, out);
}